// round 15
// baseline (speedup 1.0000x reference)
#include <cuda_runtime.h>
#include <cuda_bf16.h>
#include <cstdint>

#define BDIM 64
#define TDIM 512
#define INDIM 128
#define HDIM 512
#define G3 (3*HDIM)

// ---------------- static device scratch ----------------
__device__ float g_xg[(size_t)BDIM * TDIM * G3];
__device__ float g_h[2][BDIM * HDIM];
__device__ __align__(128) unsigned g_bar[4][32];
#define AMAX ((size_t)BDIM * TDIM * HDIM)
__device__ __nv_bfloat16 g_ahi[AMAX], g_alo[AMAX];
__device__ __nv_bfloat16 g_whi[G3 * HDIM], g_wlo[G3 * HDIM];

typedef unsigned long long ull;

__device__ __forceinline__ float sigm(float x) { return 1.f / (1.f + __expf(-x)); }
__device__ __forceinline__ float tanh_fast(float x) {
    float e = __expf(2.f * x);
    return 1.f - 2.f / (e + 1.f);
}
__device__ __forceinline__ uint32_t smem_u32(const void* p) {
    uint32_t a;
    asm("{ .reg .u64 t; cvta.to.shared.u64 t, %1; cvt.u32.u64 %0, t; }" : "=r"(a) : "l"(p));
    return a;
}
__device__ __forceinline__ void cp16(uint32_t saddr, const void* g) {
    asm volatile("cp.async.cg.shared.global [%0], [%1], 16;" :: "r"(saddr), "l"(g));
}
__device__ __forceinline__ void ldsm4(uint32_t& r0, uint32_t& r1, uint32_t& r2, uint32_t& r3,
                                      uint32_t addr) {
    asm volatile("ldmatrix.sync.aligned.m8n8.x4.shared.b16 {%0,%1,%2,%3}, [%4];"
                 : "=r"(r0), "=r"(r1), "=r"(r2), "=r"(r3) : "r"(addr));
}
__device__ __forceinline__ void mma16816(float* d, const uint32_t* a, const uint32_t* b) {
    asm volatile(
        "mma.sync.aligned.m16n8k16.row.col.f32.bf16.bf16.f32 "
        "{%0,%1,%2,%3}, {%4,%5,%6,%7}, {%8,%9}, {%0,%1,%2,%3};"
        : "+f"(d[0]), "+f"(d[1]), "+f"(d[2]), "+f"(d[3])
        : "r"(a[0]), "r"(a[1]), "r"(a[2]), "r"(a[3]), "r"(b[0]), "r"(b[1]));
}

// fp32x4 -> packed bf16 hi/lo (uint2 = 4 bf16)
__device__ __forceinline__ void cvt_pair(float4 v, uint2& hi, uint2& lo) {
    __nv_bfloat162 h0 = __floats2bfloat162_rn(v.x, v.y);
    __nv_bfloat162 h1 = __floats2bfloat162_rn(v.z, v.w);
    float2 f0 = __bfloat1622float2(h0);
    float2 f1 = __bfloat1622float2(h1);
    __nv_bfloat162 l0 = __floats2bfloat162_rn(v.x - f0.x, v.y - f0.y);
    __nv_bfloat162 l1 = __floats2bfloat162_rn(v.z - f1.x, v.w - f1.y);
    hi.x = *reinterpret_cast<unsigned*>(&h0);
    hi.y = *reinterpret_cast<unsigned*>(&h1);
    lo.x = *reinterpret_cast<unsigned*>(&l0);
    lo.y = *reinterpret_cast<unsigned*>(&l1);
}

// ============================================================================
// fp32 -> bf16 hi/lo split (for projection GEMM operands)
// ============================================================================
__global__ void cvt_split(const float* __restrict__ x, __nv_bfloat16* __restrict__ hi,
                          __nv_bfloat16* __restrict__ lo, int n)
{
    int i = blockIdx.x * blockDim.x + threadIdx.x;
    if (i < n) {
        float v = x[i];
        __nv_bfloat16 h = __float2bfloat16(v);
        hi[i] = h;
        lo[i] = __float2bfloat16(v - __bfloat162float(h));
    }
}

// ============================================================================
// HMMA bf16 split-precision projection GEMM (R7-passing, unchanged)
// ============================================================================
#define GP 40
#define GTILE_B (128*GP*2)
#define GBUF_B (4*GTILE_B)
#define SMEM_GEMM (2*GBUF_B)

template<int K>
__global__ void __launch_bounds__(256) gemm_kernel(
    const __nv_bfloat16* __restrict__ Ahi, const __nv_bfloat16* __restrict__ Alo,
    const __nv_bfloat16* __restrict__ Whi, const __nv_bfloat16* __restrict__ Wlo,
    const float* __restrict__ bias, float* __restrict__ C)
{
    extern __shared__ __nv_bfloat16 smg[];
    const uint32_t sbase = smem_u32(smg);
    const int tid = threadIdx.x;
    const int wid = tid >> 5;
    const int lane = tid & 31;
    const int m0 = blockIdx.x * 128;
    const int n0 = blockIdx.y * 128;
    constexpr int NC = K / 32;

    const __nv_bfloat16* srcs[4] = { Ahi + (size_t)m0 * K, Alo + (size_t)m0 * K,
                                     Whi + (size_t)n0 * K, Wlo + (size_t)n0 * K };

    const int wm = (wid & 1) * 64;
    const int wn = (wid >> 1) * 32;
    const uint32_t aOff = (uint32_t)((wm + (lane & 15)) * GP + (lane >> 4) * 8) * 2;
    const uint32_t bOff = (uint32_t)((wn + (lane >> 4) * 8 + (lane & 7)) * GP
                                     + ((lane >> 3) & 1) * 8) * 2;

    float acc[4][4][4];
    #pragma unroll
    for (int mt = 0; mt < 4; mt++)
        #pragma unroll
        for (int nt = 0; nt < 4; nt++)
            #pragma unroll
            for (int q = 0; q < 4; q++) acc[mt][nt][q] = 0.f;

    auto stage = [&](int c, int p) {
        const uint32_t db = sbase + p * GBUF_B;
        #pragma unroll
        for (int t4 = 0; t4 < 4; t4++) {
            const __nv_bfloat16* s = srcs[t4] + c * 32;
            const uint32_t tb = db + t4 * GTILE_B;
            #pragma unroll
            for (int i = tid; i < 512; i += 256) {
                int r = i >> 2, ch = i & 3;
                cp16(tb + (uint32_t)(r * GP + ch * 8) * 2, s + (size_t)r * K + ch * 8);
            }
        }
        asm volatile("cp.async.commit_group;");
    };

    stage(0, 0);
    for (int c = 0; c < NC; c++) {
        const int p = c & 1;
        if (c + 1 < NC) {
            stage(c + 1, p ^ 1);
            asm volatile("cp.async.wait_group 1;");
        } else {
            asm volatile("cp.async.wait_group 0;");
        }
        __syncthreads();

        const uint32_t ab = sbase + p * GBUF_B + aOff;
        const uint32_t bb = sbase + p * GBUF_B + 2 * GTILE_B + bOff;

        #pragma unroll
        for (int k16 = 0; k16 < 2; k16++) {
            uint32_t Ah[4][4], Al[4][4], Bh[2][4], Bl[2][4];
            #pragma unroll
            for (int mt = 0; mt < 4; mt++) {
                const uint32_t a = ab + (uint32_t)(mt * 16 * GP + k16 * 16) * 2;
                ldsm4(Ah[mt][0], Ah[mt][1], Ah[mt][2], Ah[mt][3], a);
                ldsm4(Al[mt][0], Al[mt][1], Al[mt][2], Al[mt][3], a + GTILE_B);
            }
            #pragma unroll
            for (int np = 0; np < 2; np++) {
                const uint32_t b = bb + (uint32_t)(np * 16 * GP + k16 * 16) * 2;
                ldsm4(Bh[np][0], Bh[np][1], Bh[np][2], Bh[np][3], b);
                ldsm4(Bl[np][0], Bl[np][1], Bl[np][2], Bl[np][3], b + GTILE_B);
            }
            #pragma unroll
            for (int mt = 0; mt < 4; mt++)
                #pragma unroll
                for (int nt = 0; nt < 4; nt++) {
                    const uint32_t* bh = &Bh[nt >> 1][(nt & 1) * 2];
                    const uint32_t* bl = &Bl[nt >> 1][(nt & 1) * 2];
                    mma16816(acc[mt][nt], Ah[mt], bh);
                    mma16816(acc[mt][nt], Ah[mt], bl);
                    mma16816(acc[mt][nt], Al[mt], bh);
                }
        }
        __syncthreads();
    }

    const int mrow = m0 + wm + (lane >> 2);
    const int ncol = n0 + wn + (lane & 3) * 2;
    #pragma unroll
    for (int nt = 0; nt < 4; nt++) {
        const int n = ncol + nt * 8;
        const float b0 = __ldg(bias + n);
        const float b1 = __ldg(bias + n + 1);
        #pragma unroll
        for (int mt = 0; mt < 4; mt++) {
            const int m = mrow + mt * 16;
            float2 o0 = make_float2(acc[mt][nt][0] + b0, acc[mt][nt][1] + b1);
            float2 o1 = make_float2(acc[mt][nt][2] + b0, acc[mt][nt][3] + b1);
            *(float2*)&C[(size_t)m * G3 + n] = o0;
            *(float2*)&C[(size_t)(m + 8) * G3 + n] = o1;
        }
    }
}

// ============================================================================
// Persistent HMMA GRU scan v6 (R10 base + warp-autonomous front half):
// - per-warp poll on the single group counter, __syncwarp only.
// - warp-private coalesced staging of the warp's OWN 16x64 h slice
//   (pitch-72 region, ldsm-conflict-free) -> front block syncs deleted.
// - hold carried in a register; W_hh fragments register-resident (R10).
// - block syncs remain only around the cross-warp reduce + release.
// ============================================================================
#define HP 520
#define OFF_WLO 49920              // 48*520*2 (W staging, one time)
#define SMEM_SCAN (2*49920)        // 99840 B
// reuse after W preload:
#define HS_PITCH 72                // bf16 pitch of warp-private h tiles
#define HS_TILE_B (16*HS_PITCH*2)  // 2304 B
#define HS_WARP_B (2*HS_TILE_B)    // hi+lo = 4608 B
#define OFF_R (8*HS_WARP_B)        // 36864
#define SRP 800                    // reduce pitch (floats) per warp

template<bool WRITE_SEQ>
__global__ void __launch_bounds__(256, 1) scan_kernel(
    const float* __restrict__ W_hh, const float* __restrict__ b_hh,
    const float* __restrict__ xg, float* __restrict__ h0buf,
    float* __restrict__ h1buf,
    __nv_bfloat16* __restrict__ seq_hi, __nv_bfloat16* __restrict__ seq_lo)
{
    extern __shared__ char sms[];
    const uint32_t sb = smem_u32(sms);
    float* sR = (float*)(sms + OFF_R);

    const int tid = threadIdx.x;
    const int wid = tid >> 5;
    const int lane = tid & 31;
    const int k0 = blockIdx.x * 16;
    const int b0 = blockIdx.y * 16;

    // ---- stage W_hh hi/lo into smem (one time) ----
    for (int i = tid; i < 48 * 128; i += 256) {
        int r = i >> 7, c4 = i & 127;
        int g = r >> 4, kr = r & 15;
        float4 v = *(const float4*)&W_hh[(size_t)(g * HDIM + k0 + kr) * HDIM + c4 * 4];
        uint2 hi, lo; cvt_pair(v, hi, lo);
        *(uint2*)(sms + (r * HP + c4 * 4) * 2) = hi;
        *(uint2*)(sms + OFF_WLO + (r * HP + c4 * 4) * 2) = lo;
    }
    __syncthreads();

    // ---- preload W fragments into registers (one time) ----
    const int jb = wid * 64;   // this warp's K-slice base
    uint32_t WH[4][3][4], WL[4][3][4];
    #pragma unroll
    for (int k16 = 0; k16 < 4; k16++)
        #pragma unroll
        for (int ng = 0; ng < 3; ng++) {
            uint32_t addr = sb + (uint32_t)((ng * 16 + (lane >> 4) * 8 + (lane & 7)) * HP
                                            + jb + k16 * 16 + ((lane >> 3) & 1) * 8) * 2;
            ldsm4(WH[k16][ng][0], WH[k16][ng][1], WH[k16][ng][2], WH[k16][ng][3], addr);
            ldsm4(WL[k16][ng][0], WL[k16][ng][1], WL[k16][ng][2], WL[k16][ng][3],
                  addr + OFF_WLO);
        }
    __syncthreads();   // smem recycled: warp-private h tiles + reduce

    // ---- warp-private staging addresses ----
    const uint32_t wbHi = sb + wid * HS_WARP_B;                   // hi tile base
    const uint32_t aHi = wbHi
        + (uint32_t)((lane & 15) * HS_PITCH + (lane >> 4) * 8) * 2;
    const uint32_t aLo = aHi + HS_TILE_B;

    // ---- per-thread epilogue cell ----
    const int m = tid >> 4;
    const int kq = tid & 15;
    const int bgl = b0 + m;
    const int kg = k0 + kq;
    const float bhr = b_hh[kg];
    const float bhz = b_hh[HDIM + kg];
    const float bhn = b_hh[2 * HDIM + kg];
    const float* xgb = xg + (size_t)bgl * TDIM * G3 + kg;
    const size_t cellIdx = (size_t)bgl * HDIM + kg;

    unsigned* bar = &g_bar[blockIdx.y][0];
    float hold = 0.f;   // h(0)=0; thereafter this thread's own previous output

    for (int t = 0; t < TDIM; t++) {
        const float* hprev = (t & 1) ? h1buf : h0buf;
        float* hnext = (t & 1) ? h0buf : h1buf;

        // ---- per-warp poll on the single group counter ----
        if (lane == 0) {
            const unsigned target = 32u * (unsigned)t;
            unsigned vv;
            do {
                asm volatile("ld.acquire.gpu.global.u32 %0, [%1];"
                             : "=r"(vv) : "l"(bar) : "memory");
            } while (vv < target);
        }
        __syncwarp();

        // xg loads issued first (independent; overlap with staging)
        const float* xt = xgb + (size_t)t * G3;
        float xr = __ldcg(xt);
        float xz = __ldcg(xt + HDIM);
        float xn = __ldcg(xt + 2 * HDIM);

        // ---- warp-private staging: own 16x64 fp32 slice -> bf16 hi/lo ----
        // idx = lane + 32*j: row = idx>>4 (16 float4/row), c4 = idx&15
        #pragma unroll
        for (int j = 0; j < 8; j++) {
            const int idx = lane + 32 * j;
            const int row = idx >> 4;
            const int c4 = idx & 15;
            float4 v = __ldcg((const float4*)&hprev[(size_t)(b0 + row) * HDIM + jb + c4 * 4]);
            uint2 hi, lo; cvt_pair(v, hi, lo);
            *(uint2*)(sms + (wbHi - sb) + (row * HS_PITCH + c4 * 4) * 2) = hi;
            *(uint2*)(sms + (wbHi - sb) + HS_TILE_B + (row * HS_PITCH + c4 * 4) * 2) = lo;
        }
        __syncwarp();

        // ---- MMA: warp's K-slice of 64 (A warp-private ldsm, W in regs) ----
        float acc[6][4];
        #pragma unroll
        for (int nt = 0; nt < 6; nt++)
            #pragma unroll
            for (int q = 0; q < 4; q++) acc[nt][q] = 0.f;

        #pragma unroll
        for (int k16 = 0; k16 < 4; k16++) {
            const uint32_t ko = k16 * 32;
            uint32_t Ah[4], Al[4];
            ldsm4(Ah[0], Ah[1], Ah[2], Ah[3], aHi + ko);
            ldsm4(Al[0], Al[1], Al[2], Al[3], aLo + ko);
            #pragma unroll
            for (int ng = 0; ng < 3; ng++)
                #pragma unroll
                for (int s = 0; s < 2; s++) {
                    float* d = acc[2 * ng + s];
                    mma16816(d, Ah, &WH[k16][ng][s * 2]);
                    mma16816(d, Ah, &WL[k16][ng][s * 2]);
                    mma16816(d, Al, &WH[k16][ng][s * 2]);
                }
        }

        // ---- dump partials: sR[wid][mrow*50 + n] ----
        {
            float* outp = sR + wid * SRP + (lane >> 2) * 50 + (lane & 3) * 2;
            #pragma unroll
            for (int nt = 0; nt < 6; nt++) {
                *(float2*)&outp[nt * 8] = make_float2(acc[nt][0], acc[nt][1]);
                *(float2*)&outp[400 + nt * 8] = make_float2(acc[nt][2], acc[nt][3]);
            }
        }
        __syncthreads();

        // ---- cross-warp reduce + gates ----
        float sr = 0.f, sz = 0.f, sn = 0.f;
        #pragma unroll
        for (int w = 0; w < 8; w++) {
            const float* rr = sR + w * SRP + m * 50;
            sr += rr[kq];
            sz += rr[16 + kq];
            sn += rr[32 + kq];
        }

        float r = sigm(xr + sr + bhr);
        float z = sigm(xz + sz + bhz);
        float n = tanh_fast(xn + r * (sn + bhn));
        float hnew = (1.f - z) * n + z * hold;
        hold = hnew;

        __stcg(&hnext[cellIdx], hnew);
        if (WRITE_SEQ) {
            __nv_bfloat16 hh = __float2bfloat16(hnew);
            __nv_bfloat16 hl = __float2bfloat16(hnew - __bfloat162float(hh));
            const size_t idx = ((size_t)bgl * TDIM + t) * HDIM + kg;
            seq_hi[idx] = hh;
            seq_lo[idx] = hl;
        }

        __syncthreads();
        if (tid == 0)
            asm volatile("red.release.gpu.global.add.u32 [%0], %1;"
                         :: "l"(bar), "r"(1u) : "memory");
    }
}

// ---------------------------------------------------------------------------
__global__ void init_kernel(float* h) {
    int i = blockIdx.x * blockDim.x + threadIdx.x;
    h[i] = 0.f;
    if (i < 128) ((unsigned*)g_bar)[i] = 0u;
}

__global__ void fc_kernel(const float* __restrict__ h, const float* __restrict__ W,
                          const float* __restrict__ bias, float* __restrict__ out)
{
    const int b = blockIdx.x;
    float s = 0.f;
    for (int k = threadIdx.x; k < HDIM; k += 128)
        s += h[(size_t)b * HDIM + k] * W[k];
    __shared__ float red[128];
    red[threadIdx.x] = s; __syncthreads();
    for (int off = 64; off > 0; off >>= 1) {
        if (threadIdx.x < off) red[threadIdx.x] += red[threadIdx.x + off];
        __syncthreads();
    }
    if (threadIdx.x == 0) out[b] = red[0] + bias[0];
}

// ---------------------------------------------------------------------------
extern "C" void kernel_launch(void* const* d_in, const int* in_sizes, int n_in,
                              void* d_out, int out_size)
{
    const float* X     = (const float*)d_in[0];
    const float* W_ih0 = (const float*)d_in[1];
    const float* W_hh0 = (const float*)d_in[2];
    const float* b_ih0 = (const float*)d_in[3];
    const float* b_hh0 = (const float*)d_in[4];
    const float* W_ih1 = (const float*)d_in[5];
    const float* W_hh1 = (const float*)d_in[6];
    const float* b_ih1 = (const float*)d_in[7];
    const float* b_hh1 = (const float*)d_in[8];
    const float* fc_W  = (const float*)d_in[9];
    const float* fc_b  = (const float*)d_in[10];
    float* out = (float*)d_out;

    float *xg, *hbuf;
    __nv_bfloat16 *ahi, *alo, *whi, *wlo;
    cudaGetSymbolAddress((void**)&xg, g_xg);
    cudaGetSymbolAddress((void**)&hbuf, g_h);
    cudaGetSymbolAddress((void**)&ahi, g_ahi);
    cudaGetSymbolAddress((void**)&alo, g_alo);
    cudaGetSymbolAddress((void**)&whi, g_whi);
    cudaGetSymbolAddress((void**)&wlo, g_wlo);

    cudaFuncSetAttribute(scan_kernel<true>,
                         cudaFuncAttributeMaxDynamicSharedMemorySize, SMEM_SCAN);
    cudaFuncSetAttribute(scan_kernel<false>,
                         cudaFuncAttributeMaxDynamicSharedMemorySize, SMEM_SCAN);
    cudaFuncSetAttribute(gemm_kernel<INDIM>,
                         cudaFuncAttributeMaxDynamicSharedMemorySize, SMEM_GEMM);
    cudaFuncSetAttribute(gemm_kernel<HDIM>,
                         cudaFuncAttributeMaxDynamicSharedMemorySize, SMEM_GEMM);

    const size_t HB = (size_t)BDIM * HDIM;
    const int M = BDIM * TDIM;                 // 32768
    const dim3 ggrid(M / 128, G3 / 128);       // (256, 12)

    // ---- Layer 0 ----
    cvt_split<<<(M * INDIM + 255) / 256, 256>>>(X, ahi, alo, M * INDIM);
    cvt_split<<<(G3 * INDIM + 255) / 256, 256>>>(W_ih0, whi, wlo, G3 * INDIM);
    gemm_kernel<INDIM><<<ggrid, 256, SMEM_GEMM>>>(ahi, alo, whi, wlo, b_ih0, xg);
    init_kernel<<<128, 512>>>(hbuf);
    // scan writes h_seq directly as bf16 hi/lo into ahi/alo (layer-1 GEMM A operand)
    scan_kernel<true><<<dim3(32, 4), 256, SMEM_SCAN>>>(
        W_hh0, b_hh0, xg, hbuf, hbuf + HB, ahi, alo);

    // ---- Layer 1 ----
    cvt_split<<<(G3 * HDIM + 255) / 256, 256>>>(W_ih1, whi, wlo, G3 * HDIM);
    gemm_kernel<HDIM><<<ggrid, 256, SMEM_GEMM>>>(ahi, alo, whi, wlo, b_ih1, xg);
    init_kernel<<<128, 512>>>(hbuf);
    scan_kernel<false><<<dim3(32, 4), 256, SMEM_SCAN>>>(
        W_hh1, b_hh1, xg, hbuf, hbuf + HB, nullptr, nullptr);

    // final h (after 512 steps) sits in parity-0 buffer
    fc_kernel<<<BDIM, 128>>>(hbuf, fc_W, fc_b, out);
}

// round 16
// speedup vs baseline: 1.2750x; 1.2750x over previous
#include <cuda_runtime.h>
#include <cuda_bf16.h>
#include <cstdint>

#define BDIM 64
#define TDIM 512
#define INDIM 128
#define HDIM 512
#define G3 (3*HDIM)

// ---------------- static device scratch ----------------
__device__ float g_xg[(size_t)BDIM * TDIM * G3];
__device__ float g_h[2][BDIM * HDIM];
__device__ __align__(128) unsigned g_bar[4][32];
#define AMAX ((size_t)BDIM * TDIM * HDIM)
__device__ __nv_bfloat16 g_ahi[AMAX], g_alo[AMAX];
__device__ __nv_bfloat16 g_whi[G3 * HDIM], g_wlo[G3 * HDIM];

typedef unsigned long long ull;

__device__ __forceinline__ float sigm(float x) { return 1.f / (1.f + __expf(-x)); }
__device__ __forceinline__ float tanh_fast(float x) {
    float e = __expf(2.f * x);
    return 1.f - 2.f / (e + 1.f);
}
__device__ __forceinline__ uint32_t smem_u32(const void* p) {
    uint32_t a;
    asm("{ .reg .u64 t; cvta.to.shared.u64 t, %1; cvt.u32.u64 %0, t; }" : "=r"(a) : "l"(p));
    return a;
}
__device__ __forceinline__ void cp16(uint32_t saddr, const void* g) {
    asm volatile("cp.async.cg.shared.global [%0], [%1], 16;" :: "r"(saddr), "l"(g));
}
__device__ __forceinline__ void ldsm4(uint32_t& r0, uint32_t& r1, uint32_t& r2, uint32_t& r3,
                                      uint32_t addr) {
    asm volatile("ldmatrix.sync.aligned.m8n8.x4.shared.b16 {%0,%1,%2,%3}, [%4];"
                 : "=r"(r0), "=r"(r1), "=r"(r2), "=r"(r3) : "r"(addr));
}
__device__ __forceinline__ void mma16816(float* d, const uint32_t* a, const uint32_t* b) {
    asm volatile(
        "mma.sync.aligned.m16n8k16.row.col.f32.bf16.bf16.f32 "
        "{%0,%1,%2,%3}, {%4,%5,%6,%7}, {%8,%9}, {%0,%1,%2,%3};"
        : "+f"(d[0]), "+f"(d[1]), "+f"(d[2]), "+f"(d[3])
        : "r"(a[0]), "r"(a[1]), "r"(a[2]), "r"(a[3]), "r"(b[0]), "r"(b[1]));
}

// fp32x4 -> packed bf16 hi/lo (uint2 = 4 bf16)
__device__ __forceinline__ void cvt_pair(float4 v, uint2& hi, uint2& lo) {
    __nv_bfloat162 h0 = __floats2bfloat162_rn(v.x, v.y);
    __nv_bfloat162 h1 = __floats2bfloat162_rn(v.z, v.w);
    float2 f0 = __bfloat1622float2(h0);
    float2 f1 = __bfloat1622float2(h1);
    __nv_bfloat162 l0 = __floats2bfloat162_rn(v.x - f0.x, v.y - f0.y);
    __nv_bfloat162 l1 = __floats2bfloat162_rn(v.z - f1.x, v.w - f1.y);
    hi.x = *reinterpret_cast<unsigned*>(&h0);
    hi.y = *reinterpret_cast<unsigned*>(&h1);
    lo.x = *reinterpret_cast<unsigned*>(&l0);
    lo.y = *reinterpret_cast<unsigned*>(&l1);
}

// ============================================================================
// fp32 -> bf16 hi/lo split
// ============================================================================
__global__ void cvt_split(const float* __restrict__ x, __nv_bfloat16* __restrict__ hi,
                          __nv_bfloat16* __restrict__ lo, int n)
{
    int i = blockIdx.x * blockDim.x + threadIdx.x;
    if (i < n) {
        float v = x[i];
        __nv_bfloat16 h = __float2bfloat16(v);
        hi[i] = h;
        lo[i] = __float2bfloat16(v - __bfloat162float(h));
    }
}

// ============================================================================
// HMMA bf16 split-precision projection GEMM (R7-passing, unchanged)
// ============================================================================
#define GP 40
#define GTILE_B (128*GP*2)
#define GBUF_B (4*GTILE_B)
#define SMEM_GEMM (2*GBUF_B)

template<int K>
__global__ void __launch_bounds__(256) gemm_kernel(
    const __nv_bfloat16* __restrict__ Ahi, const __nv_bfloat16* __restrict__ Alo,
    const __nv_bfloat16* __restrict__ Whi, const __nv_bfloat16* __restrict__ Wlo,
    const float* __restrict__ bias, float* __restrict__ C)
{
    extern __shared__ __nv_bfloat16 smg[];
    const uint32_t sbase = smem_u32(smg);
    const int tid = threadIdx.x;
    const int wid = tid >> 5;
    const int lane = tid & 31;
    const int m0 = blockIdx.x * 128;
    const int n0 = blockIdx.y * 128;
    constexpr int NC = K / 32;

    const __nv_bfloat16* srcs[4] = { Ahi + (size_t)m0 * K, Alo + (size_t)m0 * K,
                                     Whi + (size_t)n0 * K, Wlo + (size_t)n0 * K };

    const int wm = (wid & 1) * 64;
    const int wn = (wid >> 1) * 32;
    const uint32_t aOff = (uint32_t)((wm + (lane & 15)) * GP + (lane >> 4) * 8) * 2;
    const uint32_t bOff = (uint32_t)((wn + (lane >> 4) * 8 + (lane & 7)) * GP
                                     + ((lane >> 3) & 1) * 8) * 2;

    float acc[4][4][4];
    #pragma unroll
    for (int mt = 0; mt < 4; mt++)
        #pragma unroll
        for (int nt = 0; nt < 4; nt++)
            #pragma unroll
            for (int q = 0; q < 4; q++) acc[mt][nt][q] = 0.f;

    auto stage = [&](int c, int p) {
        const uint32_t db = sbase + p * GBUF_B;
        #pragma unroll
        for (int t4 = 0; t4 < 4; t4++) {
            const __nv_bfloat16* s = srcs[t4] + c * 32;
            const uint32_t tb = db + t4 * GTILE_B;
            #pragma unroll
            for (int i = tid; i < 512; i += 256) {
                int r = i >> 2, ch = i & 3;
                cp16(tb + (uint32_t)(r * GP + ch * 8) * 2, s + (size_t)r * K + ch * 8);
            }
        }
        asm volatile("cp.async.commit_group;");
    };

    stage(0, 0);
    for (int c = 0; c < NC; c++) {
        const int p = c & 1;
        if (c + 1 < NC) {
            stage(c + 1, p ^ 1);
            asm volatile("cp.async.wait_group 1;");
        } else {
            asm volatile("cp.async.wait_group 0;");
        }
        __syncthreads();

        const uint32_t ab = sbase + p * GBUF_B + aOff;
        const uint32_t bb = sbase + p * GBUF_B + 2 * GTILE_B + bOff;

        #pragma unroll
        for (int k16 = 0; k16 < 2; k16++) {
            uint32_t Ah[4][4], Al[4][4], Bh[2][4], Bl[2][4];
            #pragma unroll
            for (int mt = 0; mt < 4; mt++) {
                const uint32_t a = ab + (uint32_t)(mt * 16 * GP + k16 * 16) * 2;
                ldsm4(Ah[mt][0], Ah[mt][1], Ah[mt][2], Ah[mt][3], a);
                ldsm4(Al[mt][0], Al[mt][1], Al[mt][2], Al[mt][3], a + GTILE_B);
            }
            #pragma unroll
            for (int np = 0; np < 2; np++) {
                const uint32_t b = bb + (uint32_t)(np * 16 * GP + k16 * 16) * 2;
                ldsm4(Bh[np][0], Bh[np][1], Bh[np][2], Bh[np][3], b);
                ldsm4(Bl[np][0], Bl[np][1], Bl[np][2], Bl[np][3], b + GTILE_B);
            }
            #pragma unroll
            for (int mt = 0; mt < 4; mt++)
                #pragma unroll
                for (int nt = 0; nt < 4; nt++) {
                    const uint32_t* bh = &Bh[nt >> 1][(nt & 1) * 2];
                    const uint32_t* bl = &Bl[nt >> 1][(nt & 1) * 2];
                    mma16816(acc[mt][nt], Ah[mt], bh);
                    mma16816(acc[mt][nt], Ah[mt], bl);
                    mma16816(acc[mt][nt], Al[mt], bh);
                }
        }
        __syncthreads();
    }

    const int mrow = m0 + wm + (lane >> 2);
    const int ncol = n0 + wn + (lane & 3) * 2;
    #pragma unroll
    for (int nt = 0; nt < 4; nt++) {
        const int n = ncol + nt * 8;
        const float b0 = __ldg(bias + n);
        const float b1 = __ldg(bias + n + 1);
        #pragma unroll
        for (int mt = 0; mt < 4; mt++) {
            const int m = mrow + mt * 16;
            float2 o0 = make_float2(acc[mt][nt][0] + b0, acc[mt][nt][1] + b1);
            float2 o1 = make_float2(acc[mt][nt][2] + b0, acc[mt][nt][3] + b1);
            *(float2*)&C[(size_t)m * G3 + n] = o0;
            *(float2*)&C[(size_t)(m + 8) * G3 + n] = o1;
        }
    }
}

// ============================================================================
// Persistent HMMA GRU scan v3 (= R8 structure + register-resident W + bf16 seq):
// - W_hh fragments preloaded into registers once.
// - h staged per step via COALESCED smem path + ldsm.
// - smem reuse: W staging region recycled as h hi/lo staging + reduce buffers.
// ============================================================================
#define HP 520
#define OFF_WLO 49920              // 48*520*2
#define SMEM_SCAN (2*49920)        // 99840 B
// after W preload, region reused:
#define OFF_HHI 0
#define OFF_HLO 16640              // 16*520*2
#define OFF_R   33280
#define SRP 800                    // reduce pitch (floats) per warp

template<bool WRITE_SEQ>
__global__ void __launch_bounds__(256, 1) scan_kernel(
    const float* __restrict__ W_hh, const float* __restrict__ b_hh,
    const float* __restrict__ xg, float* __restrict__ h0buf,
    float* __restrict__ h1buf,
    __nv_bfloat16* __restrict__ seq_hi, __nv_bfloat16* __restrict__ seq_lo)
{
    extern __shared__ char sms[];
    const uint32_t sb = smem_u32(sms);
    float* sR = (float*)(sms + OFF_R);

    const int tid = threadIdx.x;
    const int wid = tid >> 5;
    const int lane = tid & 31;
    const int k0 = blockIdx.x * 16;
    const int b0 = blockIdx.y * 16;

    // ---- stage W_hh hi/lo into smem (one time) ----
    for (int i = tid; i < 48 * 128; i += 256) {
        int r = i >> 7, c4 = i & 127;
        int g = r >> 4, kr = r & 15;
        float4 v = *(const float4*)&W_hh[(size_t)(g * HDIM + k0 + kr) * HDIM + c4 * 4];
        uint2 hi, lo; cvt_pair(v, hi, lo);
        *(uint2*)(sms + (r * HP + c4 * 4) * 2) = hi;
        *(uint2*)(sms + OFF_WLO + (r * HP + c4 * 4) * 2) = lo;
    }
    __syncthreads();

    // ---- preload W fragments into registers (one time) ----
    const int jb = wid * 64;   // this warp's K-slice base
    uint32_t WH[4][3][4], WL[4][3][4];
    #pragma unroll
    for (int k16 = 0; k16 < 4; k16++)
        #pragma unroll
        for (int ng = 0; ng < 3; ng++) {
            uint32_t addr = sb + (uint32_t)((ng * 16 + (lane >> 4) * 8 + (lane & 7)) * HP
                                            + jb + k16 * 16 + ((lane >> 3) & 1) * 8) * 2;
            ldsm4(WH[k16][ng][0], WH[k16][ng][1], WH[k16][ng][2], WH[k16][ng][3], addr);
            ldsm4(WL[k16][ng][0], WL[k16][ng][1], WL[k16][ng][2], WL[k16][ng][3],
                  addr + OFF_WLO);
        }
    __syncthreads();   // smem region now recycled for h staging + reduce

    // ---- A-side ldsm base (canonical layout) ----
    const uint32_t aHi = sb + OFF_HHI
        + (uint32_t)((lane & 15) * HP + jb + (lane >> 4) * 8) * 2;
    const uint32_t aLo = aHi + (OFF_HLO - OFF_HHI);

    // ---- per-thread epilogue cell ----
    const int m = tid >> 4;
    const int kq = tid & 15;
    const int bgl = b0 + m;
    const int kg = k0 + kq;
    const float bhr = b_hh[kg];
    const float bhz = b_hh[HDIM + kg];
    const float bhn = b_hh[2 * HDIM + kg];
    const float* xgb = xg + (size_t)bgl * TDIM * G3 + kg;

    unsigned* bar = &g_bar[blockIdx.y][0];

    for (int t = 0; t < TDIM; t++) {
        const float* hprev = (t & 1) ? h1buf : h0buf;
        float* hnext = (t & 1) ? h0buf : h1buf;

        if (tid == 0) {
            const unsigned target = 32u * (unsigned)t;
            unsigned vv;
            do {
                asm volatile("ld.acquire.gpu.global.u32 %0, [%1];"
                             : "=r"(vv) : "l"(bar) : "memory");
            } while (vv < target);
        }
        __syncthreads();

        // stage h tile: 16 rows x 512, fp32 -> bf16 hi/lo (coalesced)
        #pragma unroll
        for (int i = tid; i < 16 * 128; i += 256) {
            int r = i >> 7, c4 = i & 127;
            float4 v = __ldcg((const float4*)&hprev[(size_t)(b0 + r) * HDIM + c4 * 4]);
            uint2 hi, lo; cvt_pair(v, hi, lo);
            *(uint2*)(sms + OFF_HHI + (r * HP + c4 * 4) * 2) = hi;
            *(uint2*)(sms + OFF_HLO + (r * HP + c4 * 4) * 2) = lo;
        }
        // independent prefetches (overlap with staging latency)
        float hold = __ldcg(&hprev[(size_t)bgl * HDIM + kg]);
        const float* xt = xgb + (size_t)t * G3;
        float xr = __ldcg(xt);
        float xz = __ldcg(xt + HDIM);
        float xn = __ldcg(xt + 2 * HDIM);
        __syncthreads();

        // ---- MMA: warp's K-slice of 64 (A from smem ldsm, W from regs) ----
        float acc[6][4];
        #pragma unroll
        for (int nt = 0; nt < 6; nt++)
            #pragma unroll
            for (int q = 0; q < 4; q++) acc[nt][q] = 0.f;

        #pragma unroll
        for (int k16 = 0; k16 < 4; k16++) {
            const uint32_t ko = k16 * 32;
            uint32_t Ah[4], Al[4];
            ldsm4(Ah[0], Ah[1], Ah[2], Ah[3], aHi + ko);
            ldsm4(Al[0], Al[1], Al[2], Al[3], aLo + ko);
            #pragma unroll
            for (int ng = 0; ng < 3; ng++)
                #pragma unroll
                for (int s = 0; s < 2; s++) {
                    float* d = acc[2 * ng + s];
                    mma16816(d, Ah, &WH[k16][ng][s * 2]);
                    mma16816(d, Ah, &WL[k16][ng][s * 2]);
                    mma16816(d, Al, &WH[k16][ng][s * 2]);
                }
        }

        // ---- dump partials: sR[wid][mrow*50 + n] ----
        {
            float* outp = sR + wid * SRP + (lane >> 2) * 50 + (lane & 3) * 2;
            #pragma unroll
            for (int nt = 0; nt < 6; nt++) {
                *(float2*)&outp[nt * 8] = make_float2(acc[nt][0], acc[nt][1]);
                *(float2*)&outp[400 + nt * 8] = make_float2(acc[nt][2], acc[nt][3]);
            }
        }
        __syncthreads();

        // ---- cross-warp reduce + gates ----
        float sr = 0.f, sz = 0.f, sn = 0.f;
        #pragma unroll
        for (int w = 0; w < 8; w++) {
            const float* rr = sR + w * SRP + m * 50;
            sr += rr[kq];
            sz += rr[16 + kq];
            sn += rr[32 + kq];
        }

        float r = sigm(xr + sr + bhr);
        float z = sigm(xz + sz + bhz);
        float n = tanh_fast(xn + r * (sn + bhn));
        float hnew = (1.f - z) * n + z * hold;

        __stcg(&hnext[(size_t)bgl * HDIM + kg], hnew);
        if (WRITE_SEQ) {
            __nv_bfloat16 hh = __float2bfloat16(hnew);
            __nv_bfloat16 hl = __float2bfloat16(hnew - __bfloat162float(hh));
            const size_t idx = ((size_t)bgl * TDIM + t) * HDIM + kg;
            seq_hi[idx] = hh;
            seq_lo[idx] = hl;
        }

        __syncthreads();
        if (tid == 0)
            asm volatile("red.release.gpu.global.add.u32 [%0], %1;"
                         :: "l"(bar), "r"(1u) : "memory");
    }
}

// ---------------------------------------------------------------------------
__global__ void init_kernel(float* h) {
    int i = blockIdx.x * blockDim.x + threadIdx.x;
    h[i] = 0.f;
    if (i < 128) ((unsigned*)g_bar)[i] = 0u;
}

__global__ void fc_kernel(const float* __restrict__ h, const float* __restrict__ W,
                          const float* __restrict__ bias, float* __restrict__ out)
{
    const int b = blockIdx.x;
    float s = 0.f;
    for (int k = threadIdx.x; k < HDIM; k += 128)
        s += h[(size_t)b * HDIM + k] * W[k];
    __shared__ float red[128];
    red[threadIdx.x] = s; __syncthreads();
    for (int off = 64; off > 0; off >>= 1) {
        if (threadIdx.x < off) red[threadIdx.x] += red[threadIdx.x + off];
        __syncthreads();
    }
    if (threadIdx.x == 0) out[b] = red[0] + bias[0];
}

// ---------------------------------------------------------------------------
extern "C" void kernel_launch(void* const* d_in, const int* in_sizes, int n_in,
                              void* d_out, int out_size)
{
    const float* X     = (const float*)d_in[0];
    const float* W_ih0 = (const float*)d_in[1];
    const float* W_hh0 = (const float*)d_in[2];
    const float* b_ih0 = (const float*)d_in[3];
    const float* b_hh0 = (const float*)d_in[4];
    const float* W_ih1 = (const float*)d_in[5];
    const float* W_hh1 = (const float*)d_in[6];
    const float* b_ih1 = (const float*)d_in[7];
    const float* b_hh1 = (const float*)d_in[8];
    const float* fc_W  = (const float*)d_in[9];
    const float* fc_b  = (const float*)d_in[10];
    float* out = (float*)d_out;

    float *xg, *hbuf;
    __nv_bfloat16 *ahi, *alo, *whi, *wlo;
    cudaGetSymbolAddress((void**)&xg, g_xg);
    cudaGetSymbolAddress((void**)&hbuf, g_h);
    cudaGetSymbolAddress((void**)&ahi, g_ahi);
    cudaGetSymbolAddress((void**)&alo, g_alo);
    cudaGetSymbolAddress((void**)&whi, g_whi);
    cudaGetSymbolAddress((void**)&wlo, g_wlo);

    cudaFuncSetAttribute(scan_kernel<true>,
                         cudaFuncAttributeMaxDynamicSharedMemorySize, SMEM_SCAN);
    cudaFuncSetAttribute(scan_kernel<false>,
                         cudaFuncAttributeMaxDynamicSharedMemorySize, SMEM_SCAN);
    cudaFuncSetAttribute(gemm_kernel<INDIM>,
                         cudaFuncAttributeMaxDynamicSharedMemorySize, SMEM_GEMM);
    cudaFuncSetAttribute(gemm_kernel<HDIM>,
                         cudaFuncAttributeMaxDynamicSharedMemorySize, SMEM_GEMM);

    const size_t HB = (size_t)BDIM * HDIM;
    const int M = BDIM * TDIM;                 // 32768
    const dim3 ggrid(M / 128, G3 / 128);       // (256, 12)

    // ---- Layer 0 ----
    cvt_split<<<(M * INDIM + 255) / 256, 256>>>(X, ahi, alo, M * INDIM);
    cvt_split<<<(G3 * INDIM + 255) / 256, 256>>>(W_ih0, whi, wlo, G3 * INDIM);
    gemm_kernel<INDIM><<<ggrid, 256, SMEM_GEMM>>>(ahi, alo, whi, wlo, b_ih0, xg);
    init_kernel<<<128, 512>>>(hbuf);
    // scan writes h_seq directly as bf16 hi/lo into ahi/alo (layer-1 GEMM A operand)
    scan_kernel<true><<<dim3(32, 4), 256, SMEM_SCAN>>>(
        W_hh0, b_hh0, xg, hbuf, hbuf + HB, ahi, alo);

    // ---- Layer 1 ----
    cvt_split<<<(G3 * HDIM + 255) / 256, 256>>>(W_ih1, whi, wlo, G3 * HDIM);
    gemm_kernel<HDIM><<<ggrid, 256, SMEM_GEMM>>>(ahi, alo, whi, wlo, b_ih1, xg);
    init_kernel<<<128, 512>>>(hbuf);
    scan_kernel<false><<<dim3(32, 4), 256, SMEM_SCAN>>>(
        W_hh1, b_hh1, xg, hbuf, hbuf + HB, nullptr, nullptr);

    // final h (after 512 steps) sits in parity-0 buffer
    fc_kernel<<<BDIM, 128>>>(hbuf, fc_W, fc_b, out);
}

// round 17
// speedup vs baseline: 1.2786x; 1.0028x over previous
#include <cuda_runtime.h>
#include <cuda_bf16.h>
#include <cstdint>

#define BDIM 64
#define TDIM 512
#define INDIM 128
#define HDIM 512
#define G3 (3*HDIM)

// ---------------- static device scratch ----------------
__device__ float g_xg[(size_t)BDIM * TDIM * G3];
__device__ float g_h[2][BDIM * HDIM];
__device__ __align__(128) unsigned g_bar[4][32];
#define AMAX ((size_t)BDIM * TDIM * HDIM)
__device__ __nv_bfloat16 g_ahi[AMAX], g_alo[AMAX];
__device__ __nv_bfloat16 g_whi[G3 * HDIM], g_wlo[G3 * HDIM];

typedef unsigned long long ull;

__device__ __forceinline__ float sigm(float x) { return 1.f / (1.f + __expf(-x)); }
__device__ __forceinline__ float tanh_fast(float x) {
    float e = __expf(2.f * x);
    return 1.f - 2.f / (e + 1.f);
}
__device__ __forceinline__ uint32_t smem_u32(const void* p) {
    uint32_t a;
    asm("{ .reg .u64 t; cvta.to.shared.u64 t, %1; cvt.u32.u64 %0, t; }" : "=r"(a) : "l"(p));
    return a;
}
__device__ __forceinline__ void cp16(uint32_t saddr, const void* g) {
    asm volatile("cp.async.cg.shared.global [%0], [%1], 16;" :: "r"(saddr), "l"(g));
}
__device__ __forceinline__ void ldsm4(uint32_t& r0, uint32_t& r1, uint32_t& r2, uint32_t& r3,
                                      uint32_t addr) {
    asm volatile("ldmatrix.sync.aligned.m8n8.x4.shared.b16 {%0,%1,%2,%3}, [%4];"
                 : "=r"(r0), "=r"(r1), "=r"(r2), "=r"(r3) : "r"(addr));
}
__device__ __forceinline__ void mma16816(float* d, const uint32_t* a, const uint32_t* b) {
    asm volatile(
        "mma.sync.aligned.m16n8k16.row.col.f32.bf16.bf16.f32 "
        "{%0,%1,%2,%3}, {%4,%5,%6,%7}, {%8,%9}, {%0,%1,%2,%3};"
        : "+f"(d[0]), "+f"(d[1]), "+f"(d[2]), "+f"(d[3])
        : "r"(a[0]), "r"(a[1]), "r"(a[2]), "r"(a[3]), "r"(b[0]), "r"(b[1]));
}

// fp32x4 -> packed bf16 hi/lo (uint2 = 4 bf16)
__device__ __forceinline__ void cvt_pair(float4 v, uint2& hi, uint2& lo) {
    __nv_bfloat162 h0 = __floats2bfloat162_rn(v.x, v.y);
    __nv_bfloat162 h1 = __floats2bfloat162_rn(v.z, v.w);
    float2 f0 = __bfloat1622float2(h0);
    float2 f1 = __bfloat1622float2(h1);
    __nv_bfloat162 l0 = __floats2bfloat162_rn(v.x - f0.x, v.y - f0.y);
    __nv_bfloat162 l1 = __floats2bfloat162_rn(v.z - f1.x, v.w - f1.y);
    hi.x = *reinterpret_cast<unsigned*>(&h0);
    hi.y = *reinterpret_cast<unsigned*>(&h1);
    lo.x = *reinterpret_cast<unsigned*>(&l0);
    lo.y = *reinterpret_cast<unsigned*>(&l1);
}

// ============================================================================
// fp32 -> bf16 hi/lo split
// ============================================================================
__global__ void cvt_split(const float* __restrict__ x, __nv_bfloat16* __restrict__ hi,
                          __nv_bfloat16* __restrict__ lo, int n)
{
    int i = blockIdx.x * blockDim.x + threadIdx.x;
    if (i < n) {
        float v = x[i];
        __nv_bfloat16 h = __float2bfloat16(v);
        hi[i] = h;
        lo[i] = __float2bfloat16(v - __bfloat162float(h));
    }
}

// ============================================================================
// HMMA bf16 split-precision projection GEMM
// (R7 structure; 2 blocks/SM for latency hiding — the ONLY change this round)
// ============================================================================
#define GP 40
#define GTILE_B (128*GP*2)
#define GBUF_B (4*GTILE_B)
#define SMEM_GEMM (2*GBUF_B)

template<int K>
__global__ void __launch_bounds__(256, 2) gemm_kernel(
    const __nv_bfloat16* __restrict__ Ahi, const __nv_bfloat16* __restrict__ Alo,
    const __nv_bfloat16* __restrict__ Whi, const __nv_bfloat16* __restrict__ Wlo,
    const float* __restrict__ bias, float* __restrict__ C)
{
    extern __shared__ __nv_bfloat16 smg[];
    const uint32_t sbase = smem_u32(smg);
    const int tid = threadIdx.x;
    const int wid = tid >> 5;
    const int lane = tid & 31;
    const int m0 = blockIdx.x * 128;
    const int n0 = blockIdx.y * 128;
    constexpr int NC = K / 32;

    const __nv_bfloat16* srcs[4] = { Ahi + (size_t)m0 * K, Alo + (size_t)m0 * K,
                                     Whi + (size_t)n0 * K, Wlo + (size_t)n0 * K };

    const int wm = (wid & 1) * 64;
    const int wn = (wid >> 1) * 32;
    const uint32_t aOff = (uint32_t)((wm + (lane & 15)) * GP + (lane >> 4) * 8) * 2;
    const uint32_t bOff = (uint32_t)((wn + (lane >> 4) * 8 + (lane & 7)) * GP
                                     + ((lane >> 3) & 1) * 8) * 2;

    float acc[4][4][4];
    #pragma unroll
    for (int mt = 0; mt < 4; mt++)
        #pragma unroll
        for (int nt = 0; nt < 4; nt++)
            #pragma unroll
            for (int q = 0; q < 4; q++) acc[mt][nt][q] = 0.f;

    auto stage = [&](int c, int p) {
        const uint32_t db = sbase + p * GBUF_B;
        #pragma unroll
        for (int t4 = 0; t4 < 4; t4++) {
            const __nv_bfloat16* s = srcs[t4] + c * 32;
            const uint32_t tb = db + t4 * GTILE_B;
            #pragma unroll
            for (int i = tid; i < 512; i += 256) {
                int r = i >> 2, ch = i & 3;
                cp16(tb + (uint32_t)(r * GP + ch * 8) * 2, s + (size_t)r * K + ch * 8);
            }
        }
        asm volatile("cp.async.commit_group;");
    };

    stage(0, 0);
    for (int c = 0; c < NC; c++) {
        const int p = c & 1;
        if (c + 1 < NC) {
            stage(c + 1, p ^ 1);
            asm volatile("cp.async.wait_group 1;");
        } else {
            asm volatile("cp.async.wait_group 0;");
        }
        __syncthreads();

        const uint32_t ab = sbase + p * GBUF_B + aOff;
        const uint32_t bb = sbase + p * GBUF_B + 2 * GTILE_B + bOff;

        #pragma unroll
        for (int k16 = 0; k16 < 2; k16++) {
            uint32_t Ah[4][4], Al[4][4], Bh[2][4], Bl[2][4];
            #pragma unroll
            for (int mt = 0; mt < 4; mt++) {
                const uint32_t a = ab + (uint32_t)(mt * 16 * GP + k16 * 16) * 2;
                ldsm4(Ah[mt][0], Ah[mt][1], Ah[mt][2], Ah[mt][3], a);
                ldsm4(Al[mt][0], Al[mt][1], Al[mt][2], Al[mt][3], a + GTILE_B);
            }
            #pragma unroll
            for (int np = 0; np < 2; np++) {
                const uint32_t b = bb + (uint32_t)(np * 16 * GP + k16 * 16) * 2;
                ldsm4(Bh[np][0], Bh[np][1], Bh[np][2], Bh[np][3], b);
                ldsm4(Bl[np][0], Bl[np][1], Bl[np][2], Bl[np][3], b + GTILE_B);
            }
            #pragma unroll
            for (int mt = 0; mt < 4; mt++)
                #pragma unroll
                for (int nt = 0; nt < 4; nt++) {
                    const uint32_t* bh = &Bh[nt >> 1][(nt & 1) * 2];
                    const uint32_t* bl = &Bl[nt >> 1][(nt & 1) * 2];
                    mma16816(acc[mt][nt], Ah[mt], bh);
                    mma16816(acc[mt][nt], Ah[mt], bl);
                    mma16816(acc[mt][nt], Al[mt], bh);
                }
        }
        __syncthreads();
    }

    const int mrow = m0 + wm + (lane >> 2);
    const int ncol = n0 + wn + (lane & 3) * 2;
    #pragma unroll
    for (int nt = 0; nt < 4; nt++) {
        const int n = ncol + nt * 8;
        const float b0 = __ldg(bias + n);
        const float b1 = __ldg(bias + n + 1);
        #pragma unroll
        for (int mt = 0; mt < 4; mt++) {
            const int m = mrow + mt * 16;
            float2 o0 = make_float2(acc[mt][nt][0] + b0, acc[mt][nt][1] + b1);
            float2 o1 = make_float2(acc[mt][nt][2] + b0, acc[mt][nt][3] + b1);
            *(float2*)&C[(size_t)m * G3 + n] = o0;
            *(float2*)&C[(size_t)(m + 8) * G3 + n] = o1;
        }
    }
}

// ============================================================================
// Persistent HMMA GRU scan (R10/R16 — FROZEN, byte-identical)
// ============================================================================
#define HP 520
#define OFF_WLO 49920              // 48*520*2
#define SMEM_SCAN (2*49920)        // 99840 B
// after W preload, region reused:
#define OFF_HHI 0
#define OFF_HLO 16640              // 16*520*2
#define OFF_R   33280
#define SRP 800                    // reduce pitch (floats) per warp

template<bool WRITE_SEQ>
__global__ void __launch_bounds__(256, 1) scan_kernel(
    const float* __restrict__ W_hh, const float* __restrict__ b_hh,
    const float* __restrict__ xg, float* __restrict__ h0buf,
    float* __restrict__ h1buf,
    __nv_bfloat16* __restrict__ seq_hi, __nv_bfloat16* __restrict__ seq_lo)
{
    extern __shared__ char sms[];
    const uint32_t sb = smem_u32(sms);
    float* sR = (float*)(sms + OFF_R);

    const int tid = threadIdx.x;
    const int wid = tid >> 5;
    const int lane = tid & 31;
    const int k0 = blockIdx.x * 16;
    const int b0 = blockIdx.y * 16;

    // ---- stage W_hh hi/lo into smem (one time) ----
    for (int i = tid; i < 48 * 128; i += 256) {
        int r = i >> 7, c4 = i & 127;
        int g = r >> 4, kr = r & 15;
        float4 v = *(const float4*)&W_hh[(size_t)(g * HDIM + k0 + kr) * HDIM + c4 * 4];
        uint2 hi, lo; cvt_pair(v, hi, lo);
        *(uint2*)(sms + (r * HP + c4 * 4) * 2) = hi;
        *(uint2*)(sms + OFF_WLO + (r * HP + c4 * 4) * 2) = lo;
    }
    __syncthreads();

    // ---- preload W fragments into registers (one time) ----
    const int jb = wid * 64;   // this warp's K-slice base
    uint32_t WH[4][3][4], WL[4][3][4];
    #pragma unroll
    for (int k16 = 0; k16 < 4; k16++)
        #pragma unroll
        for (int ng = 0; ng < 3; ng++) {
            uint32_t addr = sb + (uint32_t)((ng * 16 + (lane >> 4) * 8 + (lane & 7)) * HP
                                            + jb + k16 * 16 + ((lane >> 3) & 1) * 8) * 2;
            ldsm4(WH[k16][ng][0], WH[k16][ng][1], WH[k16][ng][2], WH[k16][ng][3], addr);
            ldsm4(WL[k16][ng][0], WL[k16][ng][1], WL[k16][ng][2], WL[k16][ng][3],
                  addr + OFF_WLO);
        }
    __syncthreads();   // smem region now recycled for h staging + reduce

    // ---- A-side ldsm base (canonical layout) ----
    const uint32_t aHi = sb + OFF_HHI
        + (uint32_t)((lane & 15) * HP + jb + (lane >> 4) * 8) * 2;
    const uint32_t aLo = aHi + (OFF_HLO - OFF_HHI);

    // ---- per-thread epilogue cell ----
    const int m = tid >> 4;
    const int kq = tid & 15;
    const int bgl = b0 + m;
    const int kg = k0 + kq;
    const float bhr = b_hh[kg];
    const float bhz = b_hh[HDIM + kg];
    const float bhn = b_hh[2 * HDIM + kg];
    const float* xgb = xg + (size_t)bgl * TDIM * G3 + kg;

    unsigned* bar = &g_bar[blockIdx.y][0];

    for (int t = 0; t < TDIM; t++) {
        const float* hprev = (t & 1) ? h1buf : h0buf;
        float* hnext = (t & 1) ? h0buf : h1buf;

        if (tid == 0) {
            const unsigned target = 32u * (unsigned)t;
            unsigned vv;
            do {
                asm volatile("ld.acquire.gpu.global.u32 %0, [%1];"
                             : "=r"(vv) : "l"(bar) : "memory");
            } while (vv < target);
        }
        __syncthreads();

        // stage h tile: 16 rows x 512, fp32 -> bf16 hi/lo (coalesced)
        #pragma unroll
        for (int i = tid; i < 16 * 128; i += 256) {
            int r = i >> 7, c4 = i & 127;
            float4 v = __ldcg((const float4*)&hprev[(size_t)(b0 + r) * HDIM + c4 * 4]);
            uint2 hi, lo; cvt_pair(v, hi, lo);
            *(uint2*)(sms + OFF_HHI + (r * HP + c4 * 4) * 2) = hi;
            *(uint2*)(sms + OFF_HLO + (r * HP + c4 * 4) * 2) = lo;
        }
        // independent prefetches (overlap with staging latency)
        float hold = __ldcg(&hprev[(size_t)bgl * HDIM + kg]);
        const float* xt = xgb + (size_t)t * G3;
        float xr = __ldcg(xt);
        float xz = __ldcg(xt + HDIM);
        float xn = __ldcg(xt + 2 * HDIM);
        __syncthreads();

        // ---- MMA: warp's K-slice of 64 (A from smem ldsm, W from regs) ----
        float acc[6][4];
        #pragma unroll
        for (int nt = 0; nt < 6; nt++)
            #pragma unroll
            for (int q = 0; q < 4; q++) acc[nt][q] = 0.f;

        #pragma unroll
        for (int k16 = 0; k16 < 4; k16++) {
            const uint32_t ko = k16 * 32;
            uint32_t Ah[4], Al[4];
            ldsm4(Ah[0], Ah[1], Ah[2], Ah[3], aHi + ko);
            ldsm4(Al[0], Al[1], Al[2], Al[3], aLo + ko);
            #pragma unroll
            for (int ng = 0; ng < 3; ng++)
                #pragma unroll
                for (int s = 0; s < 2; s++) {
                    float* d = acc[2 * ng + s];
                    mma16816(d, Ah, &WH[k16][ng][s * 2]);
                    mma16816(d, Ah, &WL[k16][ng][s * 2]);
                    mma16816(d, Al, &WH[k16][ng][s * 2]);
                }
        }

        // ---- dump partials: sR[wid][mrow*50 + n] ----
        {
            float* outp = sR + wid * SRP + (lane >> 2) * 50 + (lane & 3) * 2;
            #pragma unroll
            for (int nt = 0; nt < 6; nt++) {
                *(float2*)&outp[nt * 8] = make_float2(acc[nt][0], acc[nt][1]);
                *(float2*)&outp[400 + nt * 8] = make_float2(acc[nt][2], acc[nt][3]);
            }
        }
        __syncthreads();

        // ---- cross-warp reduce + gates ----
        float sr = 0.f, sz = 0.f, sn = 0.f;
        #pragma unroll
        for (int w = 0; w < 8; w++) {
            const float* rr = sR + w * SRP + m * 50;
            sr += rr[kq];
            sz += rr[16 + kq];
            sn += rr[32 + kq];
        }

        float r = sigm(xr + sr + bhr);
        float z = sigm(xz + sz + bhz);
        float n = tanh_fast(xn + r * (sn + bhn));
        float hnew = (1.f - z) * n + z * hold;

        __stcg(&hnext[(size_t)bgl * HDIM + kg], hnew);
        if (WRITE_SEQ) {
            __nv_bfloat16 hh = __float2bfloat16(hnew);
            __nv_bfloat16 hl = __float2bfloat16(hnew - __bfloat162float(hh));
            const size_t idx = ((size_t)bgl * TDIM + t) * HDIM + kg;
            seq_hi[idx] = hh;
            seq_lo[idx] = hl;
        }

        __syncthreads();
        if (tid == 0)
            asm volatile("red.release.gpu.global.add.u32 [%0], %1;"
                         :: "l"(bar), "r"(1u) : "memory");
    }
}

// ---------------------------------------------------------------------------
__global__ void init_kernel(float* h) {
    int i = blockIdx.x * blockDim.x + threadIdx.x;
    h[i] = 0.f;
    if (i < 128) ((unsigned*)g_bar)[i] = 0u;
}

__global__ void fc_kernel(const float* __restrict__ h, const float* __restrict__ W,
                          const float* __restrict__ bias, float* __restrict__ out)
{
    const int b = blockIdx.x;
    float s = 0.f;
    for (int k = threadIdx.x; k < HDIM; k += 128)
        s += h[(size_t)b * HDIM + k] * W[k];
    __shared__ float red[128];
    red[threadIdx.x] = s; __syncthreads();
    for (int off = 64; off > 0; off >>= 1) {
        if (threadIdx.x < off) red[threadIdx.x] += red[threadIdx.x + off];
        __syncthreads();
    }
    if (threadIdx.x == 0) out[b] = red[0] + bias[0];
}

// ---------------------------------------------------------------------------
extern "C" void kernel_launch(void* const* d_in, const int* in_sizes, int n_in,
                              void* d_out, int out_size)
{
    const float* X     = (const float*)d_in[0];
    const float* W_ih0 = (const float*)d_in[1];
    const float* W_hh0 = (const float*)d_in[2];
    const float* b_ih0 = (const float*)d_in[3];
    const float* b_hh0 = (const float*)d_in[4];
    const float* W_ih1 = (const float*)d_in[5];
    const float* W_hh1 = (const float*)d_in[6];
    const float* b_ih1 = (const float*)d_in[7];
    const float* b_hh1 = (const float*)d_in[8];
    const float* fc_W  = (const float*)d_in[9];
    const float* fc_b  = (const float*)d_in[10];
    float* out = (float*)d_out;

    float *xg, *hbuf;
    __nv_bfloat16 *ahi, *alo, *whi, *wlo;
    cudaGetSymbolAddress((void**)&xg, g_xg);
    cudaGetSymbolAddress((void**)&hbuf, g_h);
    cudaGetSymbolAddress((void**)&ahi, g_ahi);
    cudaGetSymbolAddress((void**)&alo, g_alo);
    cudaGetSymbolAddress((void**)&whi, g_whi);
    cudaGetSymbolAddress((void**)&wlo, g_wlo);

    cudaFuncSetAttribute(scan_kernel<true>,
                         cudaFuncAttributeMaxDynamicSharedMemorySize, SMEM_SCAN);
    cudaFuncSetAttribute(scan_kernel<false>,
                         cudaFuncAttributeMaxDynamicSharedMemorySize, SMEM_SCAN);
    cudaFuncSetAttribute(gemm_kernel<INDIM>,
                         cudaFuncAttributeMaxDynamicSharedMemorySize, SMEM_GEMM);
    cudaFuncSetAttribute(gemm_kernel<HDIM>,
                         cudaFuncAttributeMaxDynamicSharedMemorySize, SMEM_GEMM);

    const size_t HB = (size_t)BDIM * HDIM;
    const int M = BDIM * TDIM;                 // 32768
    const dim3 ggrid(M / 128, G3 / 128);       // (256, 12)

    // ---- Layer 0 ----
    cvt_split<<<(M * INDIM + 255) / 256, 256>>>(X, ahi, alo, M * INDIM);
    cvt_split<<<(G3 * INDIM + 255) / 256, 256>>>(W_ih0, whi, wlo, G3 * INDIM);
    gemm_kernel<INDIM><<<ggrid, 256, SMEM_GEMM>>>(ahi, alo, whi, wlo, b_ih0, xg);
    init_kernel<<<128, 512>>>(hbuf);
    // scan writes h_seq directly as bf16 hi/lo into ahi/alo (layer-1 GEMM A operand)
    scan_kernel<true><<<dim3(32, 4), 256, SMEM_SCAN>>>(
        W_hh0, b_hh0, xg, hbuf, hbuf + HB, ahi, alo);

    // ---- Layer 1 ----
    cvt_split<<<(G3 * HDIM + 255) / 256, 256>>>(W_ih1, whi, wlo, G3 * HDIM);
    gemm_kernel<HDIM><<<ggrid, 256, SMEM_GEMM>>>(ahi, alo, whi, wlo, b_ih1, xg);
    init_kernel<<<128, 512>>>(hbuf);
    scan_kernel<false><<<dim3(32, 4), 256, SMEM_SCAN>>>(
        W_hh1, b_hh1, xg, hbuf, hbuf + HB, nullptr, nullptr);

    // final h (after 512 steps) sits in parity-0 buffer
    fc_kernel<<<BDIM, 128>>>(hbuf, fc_W, fc_b, out);
}